// round 5
// baseline (speedup 1.0000x reference)
#include <cuda_runtime.h>

#define DD 4096
#define NSM 148
#define NW 8
#define THREADS (NW * 32)
#define NSTATIC (NSM * NW)        // 1184 static first rows
#define MATSZ ((size_t)DD * DD)

// ping-pong node buffers (scatter idx is a permutation -> fully overwritten each layer)
__device__ float g_buf0[DD];
__device__ float g_buf1[DD];
// per-layer work-stealing tickets + reset bookkeeping (zero at load; each launch leaves them zero)
__device__ unsigned g_tick[8];
__device__ unsigned g_done[8];

__device__ __forceinline__ void prefetch_l2(const void* p) {
    asm volatile("prefetch.global.L2 [%0];" :: "l"(p));
}

template<bool MASK, bool GATHER, bool SCATTER, bool PDL>
__global__ void __launch_bounds__(THREADS, 2)
gemv_layer(const float* __restrict__ W,
           const float* __restrict__ O,
           const float* __restrict__ bias,
           const float* __restrict__ src,
           const int*   __restrict__ gidx,
           const int*   __restrict__ sidx,
           float*       __restrict__ dst,
           int slot)
{
    __shared__ float s_in[DD];
    const int t    = threadIdx.x;
    const int lane = t & 31;
    const int w    = t >> 5;
    const int frow = blockIdx.x * NW + w;      // static first row for this warp

    // ---------- pre-dependency phase (overlaps upstream kernel's tail under PDL) ----------
    int gi[16];
    if (GATHER) {
        #pragma unroll
        for (int r = 0; r < 16; ++r) gi[r] = __ldg(gidx + t + r * THREADS);
    }
    {   // prefetch this warp's first W (and O) row into L2: 32 lanes x 4 lines = 16KB
        const char* wp = (const char*)(W + (size_t)frow * DD);
        #pragma unroll
        for (int i = 0; i < 4; ++i) prefetch_l2(wp + (lane * 4 + i) * 128);
        if (MASK) {
            const char* op = (const char*)(O + (size_t)frow * DD);
            #pragma unroll
            for (int i = 0; i < 4; ++i) prefetch_l2(op + (lane * 4 + i) * 128);
        }
    }

    if (PDL) cudaGridDependencySynchronize();   // wait for upstream grid completion

    // ---------- gather input vector into smem (L1 bypass: freshly written by other SMs) ----------
    #pragma unroll
    for (int r = 0; r < 16; ++r) {
        const int j = t + r * THREADS;
        s_in[j] = GATHER ? __ldcg(src + gi[r]) : __ldg(src + j);
    }
    __syncthreads();
    cudaTriggerProgrammaticLaunchCompletion();  // let the next layer start its prologue

    const float4* __restrict__ s4 = reinterpret_cast<const float4*>(s_in) + lane;

    // ---------- row loop: static first row, then steal ----------
    int row = frow;
    while (row < DD) {
        const float4* __restrict__ w4 = reinterpret_cast<const float4*>(W + (size_t)row * DD) + lane;
        const float4* __restrict__ o4 = reinterpret_cast<const float4*>(O + (size_t)row * DD) + lane;
        float acc0 = 0.f, acc1 = 0.f;
        float4 wb[8], ob[8];
        #pragma unroll
        for (int base = 0; base < 32; base += 8) {
            #pragma unroll
            for (int u = 0; u < 8; ++u) wb[u] = __ldcs(w4 + (base + u) * 32);
            if (MASK) {
                #pragma unroll
                for (int u = 0; u < 8; ++u) ob[u] = __ldcs(o4 + (base + u) * 32);
            }
            #pragma unroll
            for (int u = 0; u < 8; ++u) {
                const float4 xi = s4[(base + u) * 32];
                if (MASK) {
                    acc0 = fmaf(wb[u].x * ob[u].x, xi.x, acc0);
                    acc1 = fmaf(wb[u].y * ob[u].y, xi.y, acc1);
                    acc0 = fmaf(wb[u].z * ob[u].z, xi.z, acc0);
                    acc1 = fmaf(wb[u].w * ob[u].w, xi.w, acc1);
                } else {
                    acc0 = fmaf(wb[u].x, xi.x, acc0);
                    acc1 = fmaf(wb[u].y, xi.y, acc1);
                    acc0 = fmaf(wb[u].z, xi.z, acc0);
                    acc1 = fmaf(wb[u].w, xi.w, acc1);
                }
            }
        }
        float acc = acc0 + acc1;
        #pragma unroll
        for (int off = 16; off; off >>= 1) acc += __shfl_down_sync(0xffffffffu, acc, off);
        if (lane == 0) {
            float v = fmaxf(acc + __ldg(bias + row), 0.f);
            if (SCATTER) dst[__ldg(sidx + row)] = v;
            else         dst[row] = v;
        }
        // steal next row
        unsigned nrow;
        if (lane == 0) nrow = NSTATIC + atomicAdd(&g_tick[slot], 1u);
        nrow = __shfl_sync(0xffffffffu, nrow, 0);
        row = (int)nrow;
    }

    // ---------- replay-safe counter reset: last block to finish zeroes the slot ----------
    __syncthreads();
    if (t == 0) {
        unsigned d = atomicAdd(&g_done[slot], 1u);
        if (d == NSM - 1u) {
            *(volatile unsigned*)&g_tick[slot] = 0u;
            *(volatile unsigned*)&g_done[slot] = 0u;
        }
    }
}

extern "C" void kernel_launch(void* const* d_in, const int* in_sizes, int n_in,
                              void* d_out, int out_size)
{
    const float* x       = (const float*)d_in[0];   // [D]
    const float* W_in    = (const float*)d_in[1];   // [D, D]
    const float* b_in    = (const float*)d_in[2];   // [D]
    const float* weights = (const float*)d_in[3];   // [L, D, D]
    const float* orders  = (const float*)d_in[4];   // [L, D, D]
    const float* biases  = (const float*)d_in[5];   // [L, D]
    const int*   gidx    = (const int*)d_in[6];     // [L, D]
    const int*   sidx    = (const int*)d_in[7];     // [L+1, D]
    float*       out     = (float*)d_out;           // [D]

    float *b0 = nullptr, *b1 = nullptr;
    cudaGetSymbolAddress((void**)&b0, g_buf0);
    cudaGetSymbolAddress((void**)&b1, g_buf1);

    cudaLaunchConfig_t cfg = {};
    cfg.gridDim  = dim3(NSM, 1, 1);
    cfg.blockDim = dim3(THREADS, 1, 1);
    cfg.dynamicSmemBytes = 0;
    cfg.stream = 0;

    cudaLaunchAttribute attr = {};
    attr.id = cudaLaunchAttributeProgrammaticStreamSerialization;
    attr.val.programmaticStreamSerializationAllowed = 1;

    // kernel 0: input layer (no upstream dependency -> plain launch)
    cfg.attrs = nullptr; cfg.numAttrs = 0;
    cudaLaunchKernelEx(&cfg, gemv_layer<false, false, true, false>,
                       W_in, (const float*)nullptr, b_in, x,
                       (const int*)nullptr, sidx, b0, 0);

    // layers 1..4: PDL-serialized against the previous launch
    cfg.attrs = &attr; cfg.numAttrs = 1;
    cudaLaunchKernelEx(&cfg, gemv_layer<true, true, true, true>,
                       weights, orders, biases, b0,
                       gidx, sidx + DD, b1, 1);
    cudaLaunchKernelEx(&cfg, gemv_layer<true, true, true, true>,
                       weights + MATSZ, orders + MATSZ, biases + DD, b1,
                       gidx + DD, sidx + 2 * DD, b0, 2);
    cudaLaunchKernelEx(&cfg, gemv_layer<true, true, true, true>,
                       weights + 2 * MATSZ, orders + 2 * MATSZ, biases + 2 * DD, b0,
                       gidx + 2 * DD, sidx + 3 * DD, b1, 3);
    // final layer: pre-scatter output straight to d_out
    cudaLaunchKernelEx(&cfg, gemv_layer<true, true, false, true>,
                       weights + 3 * MATSZ, orders + 3 * MATSZ, biases + 3 * DD, b1,
                       gidx + 3 * DD, (const int*)nullptr, out, 4);
}

// round 6
// speedup vs baseline: 1.0508x; 1.0508x over previous
#include <cuda_runtime.h>

#define DD 4096
#define NSM 148
#define THREADS 1024          // 32 warps, one block per SM
#define MATSZ ((size_t)DD * DD)

// ping-pong node buffers (scatter idx is a permutation -> fully overwritten each layer)
__device__ float g_buf0[DD];
__device__ float g_buf1[DD];

__device__ __forceinline__ void prefetch_l2(const void* p) {
    asm volatile("prefetch.global.L2 [%0];" :: "l"(p));
}

template<bool MASK, bool GATHER, bool SCATTER, bool PDL>
__global__ void __launch_bounds__(THREADS, 1)
gemv_layer(const float* __restrict__ W,
           const float* __restrict__ O,
           const float* __restrict__ bias,
           const float* __restrict__ src,
           const int*   __restrict__ gidx,
           const int*   __restrict__ sidx,
           float*       __restrict__ dst)
{
    __shared__ float s_in[DD];
    const int t    = threadIdx.x;
    const int lane = t & 31;
    const int w    = t >> 5;

    // static balanced row partition: block b owns [b*DD/NSM, (b+1)*DD/NSM)
    const int r_start = (int)(((long long)blockIdx.x * DD) / NSM);
    const int r_end   = (int)(((long long)(blockIdx.x + 1) * DD) / NSM);
    const int row     = r_start + w;
    const bool has_row = row < r_end;

    // ---------- pre-dependency phase: runs while the upstream kernel's stragglers finish ----------
    int gi[4];
    if (GATHER) {
        #pragma unroll
        for (int r = 0; r < 4; ++r) gi[r] = __ldg(gidx + t + r * THREADS);
    }
    if (has_row) {
        // warm L2 with the leading 8KB of this warp's W row (and O row): 2+2 lines per lane
        const char* wp = (const char*)(W + (size_t)row * DD);
        prefetch_l2(wp + lane * 128);
        prefetch_l2(wp + 4096 + lane * 128);
        if (MASK) {
            const char* op = (const char*)(O + (size_t)row * DD);
            prefetch_l2(op + lane * 128);
            prefetch_l2(op + 4096 + lane * 128);
        }
    }

    if (PDL) cudaGridDependencySynchronize();   // upstream grid fully done; its stores visible

    // ---------- gather input vector into smem (L1 bypass: written by other SMs this frame) ----------
    #pragma unroll
    for (int r = 0; r < 4; ++r) {
        const int j = t + r * THREADS;
        s_in[j] = GATHER ? __ldcg(src + gi[r]) : __ldg(src + j);
    }
    __syncthreads();
    if (PDL || !PDL) cudaTriggerProgrammaticLaunchCompletion();  // allow next layer's prologue ASAP

    if (!has_row) return;

    const float4* __restrict__ w4 = reinterpret_cast<const float4*>(W + (size_t)row * DD) + lane;
    const float4* __restrict__ s4 = reinterpret_cast<const float4*>(s_in) + lane;

    float acc0 = 0.f, acc1 = 0.f;

    if (MASK) {
        constexpr int UF = 4;                       // 4 W + 4 O float4 buffers in flight
        const float4* __restrict__ o4 = reinterpret_cast<const float4*>(O + (size_t)row * DD) + lane;
        float4 wb[UF], ob[UF];
        #pragma unroll
        for (int base = 0; base < 32; base += UF) {
            #pragma unroll
            for (int u = 0; u < UF; ++u) wb[u] = __ldcs(w4 + (base + u) * 32);
            #pragma unroll
            for (int u = 0; u < UF; ++u) ob[u] = __ldcs(o4 + (base + u) * 32);
            #pragma unroll
            for (int u = 0; u < UF; ++u) {
                const float4 xi = s4[(base + u) * 32];
                acc0 = fmaf(wb[u].x * ob[u].x, xi.x, acc0);
                acc1 = fmaf(wb[u].y * ob[u].y, xi.y, acc1);
                acc0 = fmaf(wb[u].z * ob[u].z, xi.z, acc0);
                acc1 = fmaf(wb[u].w * ob[u].w, xi.w, acc1);
            }
        }
    } else {
        constexpr int UF = 8;
        float4 wb[UF];
        #pragma unroll
        for (int base = 0; base < 32; base += UF) {
            #pragma unroll
            for (int u = 0; u < UF; ++u) wb[u] = __ldcs(w4 + (base + u) * 32);
            #pragma unroll
            for (int u = 0; u < UF; ++u) {
                const float4 xi = s4[(base + u) * 32];
                acc0 = fmaf(wb[u].x, xi.x, acc0);
                acc1 = fmaf(wb[u].y, xi.y, acc1);
                acc0 = fmaf(wb[u].z, xi.z, acc0);
                acc1 = fmaf(wb[u].w, xi.w, acc1);
            }
        }
    }

    float acc = acc0 + acc1;
    #pragma unroll
    for (int off = 16; off; off >>= 1) acc += __shfl_down_sync(0xffffffffu, acc, off);

    if (lane == 0) {
        float v = fmaxf(acc + __ldg(bias + row), 0.f);
        if (SCATTER) dst[__ldg(sidx + row)] = v;
        else         dst[row] = v;
    }
}

extern "C" void kernel_launch(void* const* d_in, const int* in_sizes, int n_in,
                              void* d_out, int out_size)
{
    const float* x       = (const float*)d_in[0];   // [D]
    const float* W_in    = (const float*)d_in[1];   // [D, D]
    const float* b_in    = (const float*)d_in[2];   // [D]
    const float* weights = (const float*)d_in[3];   // [L, D, D]
    const float* orders  = (const float*)d_in[4];   // [L, D, D]
    const float* biases  = (const float*)d_in[5];   // [L, D]
    const int*   gidx    = (const int*)d_in[6];     // [L, D]
    const int*   sidx    = (const int*)d_in[7];     // [L+1, D]
    float*       out     = (float*)d_out;           // [D]

    float *b0 = nullptr, *b1 = nullptr;
    cudaGetSymbolAddress((void**)&b0, g_buf0);
    cudaGetSymbolAddress((void**)&b1, g_buf1);

    cudaLaunchConfig_t cfg = {};
    cfg.gridDim  = dim3(NSM, 1, 1);
    cfg.blockDim = dim3(THREADS, 1, 1);
    cfg.dynamicSmemBytes = 0;
    cfg.stream = 0;

    cudaLaunchAttribute attr = {};
    attr.id = cudaLaunchAttributeProgrammaticStreamSerialization;
    attr.val.programmaticStreamSerializationAllowed = 1;

    // kernel 0: input layer (no upstream dependency -> plain launch)
    cfg.attrs = nullptr; cfg.numAttrs = 0;
    cudaLaunchKernelEx(&cfg, gemv_layer<false, false, true, false>,
                       W_in, (const float*)nullptr, b_in, x,
                       (const int*)nullptr, sidx, b0);

    // layers 1..4: PDL-serialized against the previous launch
    cfg.attrs = &attr; cfg.numAttrs = 1;
    cudaLaunchKernelEx(&cfg, gemv_layer<true, true, true, true>,
                       weights, orders, biases, b0,
                       gidx, sidx + DD, b1);
    cudaLaunchKernelEx(&cfg, gemv_layer<true, true, true, true>,
                       weights + MATSZ, orders + MATSZ, biases + DD, b1,
                       gidx + DD, sidx + 2 * DD, b0);
    cudaLaunchKernelEx(&cfg, gemv_layer<true, true, true, true>,
                       weights + 2 * MATSZ, orders + 2 * MATSZ, biases + 2 * DD, b0,
                       gidx + 2 * DD, sidx + 3 * DD, b1);
    // final layer: pre-scatter output straight to d_out
    cudaLaunchKernelEx(&cfg, gemv_layer<true, true, false, true>,
                       weights + 3 * MATSZ, orders + 3 * MATSZ, biases + 3 * DD, b1,
                       gidx + 3 * DD, (const int*)nullptr, out);
}